// round 16
// baseline (speedup 1.0000x reference)
#include <cuda_runtime.h>
#include <cuda_fp16.h>
#include <cstdint>

// Problem constants
#define NB 2
#define NV 25000
#define NTOT (NB * NV)          // 50000 points
#define EDIM 128
#define KNN 16
#define NHEAD 8

#define LDROW 72                        // halfs per smem row (144B = 9*16B)
#define CHUNK_BYTES (128 * LDROW * 2)   // 128x64 chunk = 18432 B
#define SMEM_QKV (4 * CHUNK_BYTES)      // A0,A1,W0,W1 = 73728
#define ACH_BYTES (64 * LDROW * 2)      // 64x64 chunk = 9216 B
#define SMEM_OUT (2 * ACH_BYTES + 2 * CHUNK_BYTES)  // 55296

// Scratch (device globals; no allocs allowed). All fp16.
__device__ __half g_xh [NTOT * EDIM];       // x converted to fp16
__device__ __half g_wh [4 * EDIM * EDIM];   // wq,wk,wv,wo in fp16
__device__ __half g_xq [NTOT * EDIM];
__device__ __half g_xk [NTOT * EDIM];
__device__ __half g_xv [NTOT * EDIM];
__device__ __half g_att[NTOT * EDIM];

// ---------------------------------------------------------------------------
// cp.async helpers
// ---------------------------------------------------------------------------
__device__ __forceinline__ void cp16(uint32_t dst, const void* src, bool pred) {
    asm volatile("cp.async.cg.shared.global [%0], [%1], 16, %2;"
                 :: "r"(dst), "l"(src), "r"(pred ? 16 : 0));
}
#define CP_COMMIT() asm volatile("cp.async.commit_group;")
#define CP_WAIT(n)  asm volatile("cp.async.wait_group %0;" :: "n"(n))

// Copy nr rows x 64 cols fp16 (src stride EDIM) into an smem chunk.
template<int NR, int NT>
__device__ __forceinline__ void fill_chunk(
    uint32_t sbase, const __half* __restrict__ src,
    int row0, int ko, int nrows, int tid)
{
#pragma unroll
    for (int jj = 0; jj < (NR * 8) / NT; jj++) {
        int u  = tid + jj * NT;
        int r  = u >> 3;
        int c8 = (u & 7) << 3;              // 0..56
        uint32_t dst = sbase + (uint32_t)(r * LDROW + c8) * 2;
        const __half* s = src + (size_t)(row0 + r) * EDIM + ko + c8;
        cp16(dst, s, row0 + r < nrows);
    }
}

// ---------------------------------------------------------------------------
// Pre-convert v2: fp32 -> fp16 streaming, 4 float4 per thread (MLP=4).
// ---------------------------------------------------------------------------
#define XF4 (NTOT * EDIM / 4)    // 1,600,000 float4 in x

__global__ __launch_bounds__(256) void k_convert(
    const float* __restrict__ x,
    const float* __restrict__ wq, const float* __restrict__ wk,
    const float* __restrict__ wv, const float* __restrict__ wo)
{
    const int bid = blockIdx.x;
    const int t = threadIdx.x;

    if (bid < 1600) {
        size_t base = (size_t)bid * 1024 + t;   // float4 index
#pragma unroll
        for (int jj = 0; jj < 4; jj++) {
            size_t i4 = base + jj * 256;
            if (i4 < (size_t)XF4) {
                float4 v = ((const float4*)x)[i4];
                __half2 h0 = __floats2half2_rn(v.x, v.y);
                __half2 h1 = __floats2half2_rn(v.z, v.w);
                *(uint2*)(g_xh + i4 * 4) =
                    make_uint2(*(uint32_t*)&h0, *(uint32_t*)&h1);
            }
        }
    } else {
        int wb = bid - 1600;                    // 0..15, 4 blocks per weight
        int wsel = wb >> 2;
        const float* src = (wsel == 0) ? wq : (wsel == 1) ? wk
                         : (wsel == 2) ? wv : wo;
        __half* dst = g_wh + wsel * (EDIM * EDIM);
        size_t base = (size_t)(wb & 3) * 1024 + t;  // float4 index in [0,4096)
#pragma unroll
        for (int jj = 0; jj < 4; jj++) {
            size_t i4 = base + jj * 256;
            float4 v = ((const float4*)src)[i4];
            __half2 h0 = __floats2half2_rn(v.x, v.y);
            __half2 h1 = __floats2half2_rn(v.z, v.w);
            *(uint2*)(dst + i4 * 4) =
                make_uint2(*(uint32_t*)&h0, *(uint32_t*)&h1);
        }
    }
#if __CUDA_ARCH__ >= 900
    cudaTriggerProgrammaticLaunchCompletion();
#endif
}

// ---------------------------------------------------------------------------
// QKV GEMM: 128x128 tile / 256 threads. PDL: sync before reading g_xh/g_wh.
// ---------------------------------------------------------------------------
__global__ __launch_bounds__(256) void k_qkv_f()
{
    extern __shared__ __half sm[];
    uint32_t sbase = (uint32_t)__cvta_generic_to_shared(sm);
    uint32_t Ab[2] = { sbase,                   sbase + CHUNK_BYTES };
    uint32_t Wb[2] = { sbase + 2 * CHUNK_BYTES, sbase + 3 * CHUNK_BYTES };

    const int wsel = blockIdx.y;
    const __half* Asrc = g_xh;
    const __half* Wsrc = g_wh + wsel * (EDIM * EDIM);
    __half* Yh = (wsel == 0) ? g_xq : (wsel == 1) ? g_xk : g_xv;

    const int tid  = threadIdx.x;
    const int lane = tid & 31;
    const int w    = tid >> 5;
    const int gid  = lane >> 2;
    const int tig  = lane & 3;
    const int row0 = blockIdx.x * 128;
    const int row_base = (w & 3) << 5;
    const int col_base = (w >> 2) << 6;

#if __CUDA_ARCH__ >= 900
    cudaGridDependencySynchronize();   // wait for k_convert's writes
#endif

    fill_chunk<128, 256>(Ab[0], Asrc, row0, 0, NTOT, tid);
    fill_chunk<128, 256>(Wb[0], Wsrc, 0, 0, 128, tid);
    CP_COMMIT();
    fill_chunk<128, 256>(Ab[1], Asrc, row0, 64, NTOT, tid);
    fill_chunk<128, 256>(Wb[1], Wsrc, 0, 64, 128, tid);
    CP_COMMIT();

    const int l7 = lane & 7;
    const int a_row_sel = ((lane >> 3) & 1) << 3;
    const int a_k_sel   = (lane >> 4) << 3;
    const int b_row_sel = (lane >> 4) << 3;
    const int b_k_sel   = ((lane >> 3) & 1) << 3;
    uint32_t a_off[2], b_off[4];
#pragma unroll
    for (int mt = 0; mt < 2; mt++)
        a_off[mt] = (uint32_t)((row_base + (mt << 4) + a_row_sel + l7) * LDROW + a_k_sel) * 2;
#pragma unroll
    for (int tp = 0; tp < 4; tp++)
        b_off[tp] = (uint32_t)((col_base + (tp << 4) + b_row_sel + l7) * LDROW + b_k_sel) * 2;

    float acc[2][8][4];
#pragma unroll
    for (int mt = 0; mt < 2; mt++)
#pragma unroll
        for (int t = 0; t < 8; t++)
#pragma unroll
            for (int c = 0; c < 4; c++) acc[mt][t][c] = 0.f;

#pragma unroll
    for (int step = 0; step < 2; step++) {
        if (step == 0) { CP_WAIT(1); } else { CP_WAIT(0); }
        __syncthreads();
        const uint32_t Ac = Ab[step], Wc = Wb[step];
#pragma unroll
        for (int ks = 0; ks < 4; ks++) {
            const uint32_t kofs = ks * 32;
            uint32_t a[2][4], b[8][2];
#pragma unroll
            for (int mt = 0; mt < 2; mt++)
                asm volatile(
                    "ldmatrix.sync.aligned.m8n8.x4.shared.b16 {%0,%1,%2,%3}, [%4];"
                    : "=r"(a[mt][0]), "=r"(a[mt][1]), "=r"(a[mt][2]), "=r"(a[mt][3])
                    : "r"(Ac + a_off[mt] + kofs));
#pragma unroll
            for (int tp = 0; tp < 4; tp++)
                asm volatile(
                    "ldmatrix.sync.aligned.m8n8.x4.shared.b16 {%0,%1,%2,%3}, [%4];"
                    : "=r"(b[2 * tp][0]), "=r"(b[2 * tp][1]),
                      "=r"(b[2 * tp + 1][0]), "=r"(b[2 * tp + 1][1])
                    : "r"(Wc + b_off[tp] + kofs));
#pragma unroll
            for (int mt = 0; mt < 2; mt++)
#pragma unroll
                for (int t = 0; t < 8; t++)
                    asm volatile(
                        "mma.sync.aligned.m16n8k16.row.col.f32.f16.f16.f32 "
                        "{%0,%1,%2,%3}, {%4,%5,%6,%7}, {%8,%9}, {%0,%1,%2,%3};"
                        : "+f"(acc[mt][t][0]), "+f"(acc[mt][t][1]),
                          "+f"(acc[mt][t][2]), "+f"(acc[mt][t][3])
                        : "r"(a[mt][0]), "r"(a[mt][1]), "r"(a[mt][2]), "r"(a[mt][3]),
                          "r"(b[t][0]), "r"(b[t][1]));
        }
    }

#pragma unroll
    for (int mt = 0; mt < 2; mt++) {
        int r0g = row0 + row_base + (mt << 4) + gid;
#pragma unroll
        for (int t = 0; t < 8; t++) {
            int col = col_base + (t << 3) + (tig << 1);
            if (r0g < NTOT) {
                __half2 hv = __floats2half2_rn(acc[mt][t][0], acc[mt][t][1]);
                *(uint32_t*)(Yh + (size_t)r0g * EDIM + col) = *(uint32_t*)&hv;
            }
            if (r0g + 8 < NTOT) {
                __half2 hv = __floats2half2_rn(acc[mt][t][2], acc[mt][t][3]);
                *(uint32_t*)(Yh + (size_t)(r0g + 8) * EDIM + col) = *(uint32_t*)&hv;
            }
        }
    }
#if __CUDA_ARCH__ >= 900
    cudaTriggerProgrammaticLaunchCompletion();
#endif
}

// ---------------------------------------------------------------------------
// Attention v2: shorter critical path.
//  - idx load issued FIRST; neighbor indices distributed via __shfl (no smem,
//    no __syncwarp between idx and the gathers).
//  - p-dependent loads (q head-slice, center V) hoisted before the
//    idx-dependent section so they're in flight during the gather chain.
// Numerics identical to round 9.
// ---------------------------------------------------------------------------
__global__ __launch_bounds__(128) void k_attn(const int* __restrict__ idx)
{
    const int warp = threadIdx.x >> 5;
    const int lane = threadIdx.x & 31;
    const int p = blockIdx.x * 4 + warp;
    const int b = (p >= NV) ? 1 : 0;

    const int h = lane >> 2;
    const int j = lane & 3;
    const size_t doff = (size_t)(h << 4) + (j << 2);

    // 1) idx load first (lanes 0..15); clamp; keep in a register.
    int nval = 0;
    if (lane < KNN) {
        int n = idx[(size_t)p * KNN + lane];
        n = (n < 0) ? 0 : (n >= NV ? NV - 1 : n);
        nval = b * NV + n;
    }

#if __CUDA_ARCH__ >= 900
    cudaGridDependencySynchronize();   // wait for k_qkv's g_xq/g_xk/g_xv
#endif

    // 2) p-dependent loads (independent of idx) — issue early.
    uint2 craw = *(const uint2*)(g_xv + (size_t)p * EDIM + doff);
    uint4 qu[2];
    {
        const uint4* qp = (const uint4*)(g_xq + (size_t)p * EDIM + (h << 4));
        qu[0] = qp[0]; qu[1] = qp[1];
    }

    // 3) V gathers: neighbor index via shuffle broadcast (warp converged).
    uint2 vraw[KNN];
#pragma unroll
    for (int k = 0; k < KNN; k++) {
        int gk = __shfl_sync(0xffffffffu, nval, k);
        vraw[k] = *(const uint2*)(g_xv + (size_t)gk * EDIM + doff);
    }

    // Unpack q
    float qr[16];
    {
        const __half2* qh = (const __half2*)qu;
#pragma unroll
        for (int c = 0; c < 8; c++) {
            float2 f = __half22float2(qh[c]);
            qr[2 * c] = f.x; qr[2 * c + 1] = f.y;
        }
    }

    // 4) Scores for k = 4j .. 4j+3
    float sc[4];
#pragma unroll
    for (int i = 0; i < 4; i++) {
        int k = (j << 2) | i;
        int gk = __shfl_sync(0xffffffffu, nval, k);
        const uint4* kp = (const uint4*)(g_xk + (size_t)gk * EDIM + (h << 4));
        uint4 ku[2] = { kp[0], kp[1] };
        const __half2* kh = (const __half2*)ku;
        float d = 0.f;
#pragma unroll
        for (int c = 0; c < 8; c++) {
            float2 f = __half22float2(kh[c]);
            d += qr[2 * c] * f.x + qr[2 * c + 1] * f.y;
        }
        sc[i] = d * 0.25f;  // 1/sqrt(hd=16)
    }

    // Softmax over 16 scores across the quad
    float m = fmaxf(fmaxf(sc[0], sc[1]), fmaxf(sc[2], sc[3]));
    m = fmaxf(m, __shfl_xor_sync(0xffffffffu, m, 1));
    m = fmaxf(m, __shfl_xor_sync(0xffffffffu, m, 2));
    float s = 0.f;
#pragma unroll
    for (int i = 0; i < 4; i++) { sc[i] = __expf(sc[i] - m); s += sc[i]; }
    s += __shfl_xor_sync(0xffffffffu, s, 1);
    s += __shfl_xor_sync(0xffffffffu, s, 2);
    float rinv = 1.f / s;
#pragma unroll
    for (int i = 0; i < 4; i++) sc[i] *= rinv;   // lane (h,j) holds p[k=4j+i]

    // Weighted sum of V minus center (probs via quad shuffles)
    float2 c0 = __half22float2(*(__half2*)&craw.x);
    float2 c1 = __half22float2(*(__half2*)&craw.y);
    float ax = -c0.x, ay = -c0.y, az = -c1.x, aw = -c1.y;
#pragma unroll
    for (int jp = 0; jp < 4; jp++)
#pragma unroll
        for (int i = 0; i < 4; i++) {
            float pk = __shfl_sync(0xffffffffu, sc[i], (h << 2) | jp);
            uint2 raw = vraw[(jp << 2) | i];
            float2 f0 = __half22float2(*(__half2*)&raw.x);
            float2 f1 = __half22float2(*(__half2*)&raw.y);
            ax += pk * f0.x; ay += pk * f0.y; az += pk * f1.x; aw += pk * f1.y;
        }
    __half2 o0 = __floats2half2_rn(ax, ay);
    __half2 o1 = __floats2half2_rn(az, aw);
    *(uint2*)(g_att + (size_t)p * EDIM + doff) =
        make_uint2(*(uint32_t*)&o0, *(uint32_t*)&o1);
#if __CUDA_ARCH__ >= 900
    cudaTriggerProgrammaticLaunchCompletion();
#endif
}

// ---------------------------------------------------------------------------
// Out-proj GEMM (round-15 version). PDL: Wo fill + x prefetch pre-sync.
// ---------------------------------------------------------------------------
__global__ __launch_bounds__(256) void k_out_f(
    const float* __restrict__ x, float* __restrict__ out)
{
    extern __shared__ __half sm[];
    uint32_t sbase = (uint32_t)__cvta_generic_to_shared(sm);
    uint32_t Ab[2] = { sbase,                 sbase + ACH_BYTES };
    uint32_t Wb[2] = { sbase + 2 * ACH_BYTES, sbase + 2 * ACH_BYTES + CHUNK_BYTES };

    const __half* Wsrc = g_wh + 3 * (EDIM * EDIM);

    const int tid  = threadIdx.x;
    const int lane = tid & 31;
    const int w    = tid >> 5;
    const int gid  = lane >> 2;
    const int tig  = lane & 3;
    const int row0 = blockIdx.x * 64;
    const int row_base = (w & 3) << 4;   // 0,16,32,48
    const int col_base = (w >> 2) << 6;  // 0,64

    // Pre-sync: Wo fill (transitively complete) + residual-x prefetch (input).
    fill_chunk<128, 256>(Wb[0], Wsrc, 0, 0, 128, tid);
    fill_chunk<128, 256>(Wb[1], Wsrc, 0, 64, 128, tid);
    CP_COMMIT();                                       // g0

    const int r0g = row0 + row_base + gid;
    const bool v_lo = (r0g < NTOT);
    const bool v_hi = (r0g + 8 < NTOT);
    float2 xr[2][8];
#pragma unroll
    for (int t = 0; t < 8; t++) {
        int col = col_base + (t << 3) + (tig << 1);
        xr[0][t] = v_lo ? *(const float2*)(x + (size_t)r0g * EDIM + col)
                        : make_float2(0.f, 0.f);
        xr[1][t] = v_hi ? *(const float2*)(x + (size_t)(r0g + 8) * EDIM + col)
                        : make_float2(0.f, 0.f);
    }

#if __CUDA_ARCH__ >= 900
    cudaGridDependencySynchronize();   // wait for k_attn's g_att
#endif

    fill_chunk<64, 256>(Ab[0], g_att, row0, 0, NTOT, tid);
    CP_COMMIT();                                       // g1
    fill_chunk<64, 256>(Ab[1], g_att, row0, 64, NTOT, tid);
    CP_COMMIT();                                       // g2

    const int l7 = lane & 7;
    const int a_row_sel = ((lane >> 3) & 1) << 3;
    const int a_k_sel   = (lane >> 4) << 3;
    const int b_row_sel = (lane >> 4) << 3;
    const int b_k_sel   = ((lane >> 3) & 1) << 3;
    uint32_t a_off  = (uint32_t)((row_base + a_row_sel + l7) * LDROW + a_k_sel) * 2;
    uint32_t b_off[4];
#pragma unroll
    for (int tp = 0; tp < 4; tp++)
        b_off[tp] = (uint32_t)((col_base + (tp << 4) + b_row_sel + l7) * LDROW + b_k_sel) * 2;

    float acc[8][4];
#pragma unroll
    for (int t = 0; t < 8; t++)
#pragma unroll
        for (int c = 0; c < 4; c++) acc[t][c] = 0.f;

#pragma unroll
    for (int step = 0; step < 2; step++) {
        if (step == 0) { CP_WAIT(1); } else { CP_WAIT(0); }
        __syncthreads();
        const uint32_t Ac = Ab[step], Wc = Wb[step];
#pragma unroll
        for (int ks = 0; ks < 4; ks++) {
            const uint32_t kofs = ks * 32;
            uint32_t a[4], b[8][2];
            asm volatile(
                "ldmatrix.sync.aligned.m8n8.x4.shared.b16 {%0,%1,%2,%3}, [%4];"
                : "=r"(a[0]), "=r"(a[1]), "=r"(a[2]), "=r"(a[3])
                : "r"(Ac + a_off + kofs));
#pragma unroll
            for (int tp = 0; tp < 4; tp++)
                asm volatile(
                    "ldmatrix.sync.aligned.m8n8.x4.shared.b16 {%0,%1,%2,%3}, [%4];"
                    : "=r"(b[2 * tp][0]), "=r"(b[2 * tp][1]),
                      "=r"(b[2 * tp + 1][0]), "=r"(b[2 * tp + 1][1])
                    : "r"(Wc + b_off[tp] + kofs));
#pragma unroll
            for (int t = 0; t < 8; t++)
                asm volatile(
                    "mma.sync.aligned.m16n8k16.row.col.f32.f16.f16.f32 "
                    "{%0,%1,%2,%3}, {%4,%5,%6,%7}, {%8,%9}, {%0,%1,%2,%3};"
                    : "+f"(acc[t][0]), "+f"(acc[t][1]), "+f"(acc[t][2]), "+f"(acc[t][3])
                    : "r"(a[0]), "r"(a[1]), "r"(a[2]), "r"(a[3]),
                      "r"(b[t][0]), "r"(b[t][1]));
        }
    }

#pragma unroll
    for (int t = 0; t < 8; t++) {
        int col = col_base + (t << 3) + (tig << 1);
        if (v_lo) {
            size_t off = (size_t)r0g * EDIM + col;
            *(float2*)(out + off) =
                make_float2(acc[t][0] + xr[0][t].x, acc[t][1] + xr[0][t].y);
        }
        if (v_hi) {
            size_t off = (size_t)(r0g + 8) * EDIM + col;
            *(float2*)(out + off) =
                make_float2(acc[t][2] + xr[1][t].x, acc[t][3] + xr[1][t].y);
        }
    }
}

// ---------------------------------------------------------------------------
// Launch with PDL (unchanged from round 15).
// Inputs (metadata order): x[f32], idx[i32], w_q, w_k, w_v, w_o [f32]
// ---------------------------------------------------------------------------
extern "C" void kernel_launch(void* const* d_in, const int* in_sizes, int n_in,
                              void* d_out, int out_size)
{
    const float* x   = (const float*)d_in[0];
    const int*   idx = (const int*)d_in[1];
    const float* wq  = (const float*)d_in[2];
    const float* wk  = (const float*)d_in[3];
    const float* wv  = (const float*)d_in[4];
    const float* wo  = (const float*)d_in[5];
    float*       out = (float*)d_out;

    cudaFuncSetAttribute(k_qkv_f, cudaFuncAttributeMaxDynamicSharedMemorySize, SMEM_QKV);
    cudaFuncSetAttribute(k_out_f, cudaFuncAttributeMaxDynamicSharedMemorySize, SMEM_OUT);

    cudaLaunchAttribute pdl[1];
    pdl[0].id = cudaLaunchAttributeProgrammaticStreamSerialization;
    pdl[0].val.programmaticStreamSerializationAllowed = 1;

    k_convert<<<1616, 256>>>(x, wq, wk, wv, wo);

    {
        cudaLaunchConfig_t cfg = {};
        cfg.gridDim = dim3((NTOT + 127) / 128, 3);
        cfg.blockDim = dim3(256);
        cfg.dynamicSmemBytes = SMEM_QKV;
        cfg.stream = 0;
        cfg.attrs = pdl;
        cfg.numAttrs = 1;
        cudaLaunchKernelEx(&cfg, k_qkv_f);
    }
    {
        cudaLaunchConfig_t cfg = {};
        cfg.gridDim = dim3(NTOT / 4);
        cfg.blockDim = dim3(128);
        cfg.dynamicSmemBytes = 0;
        cfg.stream = 0;
        cfg.attrs = pdl;
        cfg.numAttrs = 1;
        cudaLaunchKernelEx(&cfg, k_attn, idx);
    }
    {
        cudaLaunchConfig_t cfg = {};
        cfg.gridDim = dim3((NTOT + 63) / 64);
        cfg.blockDim = dim3(256);
        cfg.dynamicSmemBytes = SMEM_OUT;
        cfg.stream = 0;
        cfg.attrs = pdl;
        cfg.numAttrs = 1;
        cudaLaunchKernelEx(&cfg, k_out_f, x, out);
    }
}

// round 17
// speedup vs baseline: 1.0222x; 1.0222x over previous
#include <cuda_runtime.h>
#include <cuda_fp16.h>
#include <cstdint>

// Problem constants
#define NB 2
#define NV 25000
#define NTOT (NB * NV)          // 50000 points
#define EDIM 128
#define KNN 16
#define NHEAD 8

#define LDROW 72                        // halfs per smem row (144B = 9*16B)
#define CHUNK_BYTES (128 * LDROW * 2)   // 128x64 chunk = 18432 B
#define SMEM_QKV (4 * CHUNK_BYTES)      // A0,A1,W0,W1 = 73728
#define ACH_BYTES (64 * LDROW * 2)      // 64x64 chunk = 9216 B
#define SMEM_OUT (2 * ACH_BYTES + 2 * CHUNK_BYTES)  // 55296

// Scratch (device globals; no allocs allowed). All fp16.
__device__ __half g_xh [NTOT * EDIM];       // x converted to fp16
__device__ __half g_wh [4 * EDIM * EDIM];   // wq,wk,wv,wo in fp16
__device__ __half g_xq [NTOT * EDIM];
__device__ __half g_xk [NTOT * EDIM];
__device__ __half g_xv [NTOT * EDIM];
__device__ __half g_att[NTOT * EDIM];

// ---------------------------------------------------------------------------
// cp.async helpers
// ---------------------------------------------------------------------------
__device__ __forceinline__ void cp16(uint32_t dst, const void* src, bool pred) {
    asm volatile("cp.async.cg.shared.global [%0], [%1], 16, %2;"
                 :: "r"(dst), "l"(src), "r"(pred ? 16 : 0));
}
#define CP_COMMIT() asm volatile("cp.async.commit_group;")
#define CP_WAIT(n)  asm volatile("cp.async.wait_group %0;" :: "n"(n))

// Copy nr rows x 64 cols fp16 (src stride EDIM) into an smem chunk.
template<int NR, int NT>
__device__ __forceinline__ void fill_chunk(
    uint32_t sbase, const __half* __restrict__ src,
    int row0, int ko, int nrows, int tid)
{
#pragma unroll
    for (int jj = 0; jj < (NR * 8) / NT; jj++) {
        int u  = tid + jj * NT;
        int r  = u >> 3;
        int c8 = (u & 7) << 3;              // 0..56
        uint32_t dst = sbase + (uint32_t)(r * LDROW + c8) * 2;
        const __half* s = src + (size_t)(row0 + r) * EDIM + ko + c8;
        cp16(dst, s, row0 + r < nrows);
    }
}

// ---------------------------------------------------------------------------
// Pre-convert v2: fp32 -> fp16 streaming, 4 float4 per thread (MLP=4).
// ---------------------------------------------------------------------------
#define XF4 (NTOT * EDIM / 4)    // 1,600,000 float4 in x

__global__ __launch_bounds__(256) void k_convert(
    const float* __restrict__ x,
    const float* __restrict__ wq, const float* __restrict__ wk,
    const float* __restrict__ wv, const float* __restrict__ wo)
{
    const int bid = blockIdx.x;
    const int t = threadIdx.x;

    if (bid < 1600) {
        size_t base = (size_t)bid * 1024 + t;   // float4 index
#pragma unroll
        for (int jj = 0; jj < 4; jj++) {
            size_t i4 = base + jj * 256;
            if (i4 < (size_t)XF4) {
                float4 v = ((const float4*)x)[i4];
                __half2 h0 = __floats2half2_rn(v.x, v.y);
                __half2 h1 = __floats2half2_rn(v.z, v.w);
                *(uint2*)(g_xh + i4 * 4) =
                    make_uint2(*(uint32_t*)&h0, *(uint32_t*)&h1);
            }
        }
    } else {
        int wb = bid - 1600;                    // 0..15, 4 blocks per weight
        int wsel = wb >> 2;
        const float* src = (wsel == 0) ? wq : (wsel == 1) ? wk
                         : (wsel == 2) ? wv : wo;
        __half* dst = g_wh + wsel * (EDIM * EDIM);
        size_t base = (size_t)(wb & 3) * 1024 + t;  // float4 index in [0,4096)
#pragma unroll
        for (int jj = 0; jj < 4; jj++) {
            size_t i4 = base + jj * 256;
            float4 v = ((const float4*)src)[i4];
            __half2 h0 = __floats2half2_rn(v.x, v.y);
            __half2 h1 = __floats2half2_rn(v.z, v.w);
            *(uint2*)(dst + i4 * 4) =
                make_uint2(*(uint32_t*)&h0, *(uint32_t*)&h1);
        }
    }
#if __CUDA_ARCH__ >= 900
    cudaTriggerProgrammaticLaunchCompletion();
#endif
}

// ---------------------------------------------------------------------------
// QKV GEMM: 128x128 tile / 256 threads. PDL: sync before reading g_xh/g_wh.
// ---------------------------------------------------------------------------
__global__ __launch_bounds__(256) void k_qkv_f()
{
    extern __shared__ __half sm[];
    uint32_t sbase = (uint32_t)__cvta_generic_to_shared(sm);
    uint32_t Ab[2] = { sbase,                   sbase + CHUNK_BYTES };
    uint32_t Wb[2] = { sbase + 2 * CHUNK_BYTES, sbase + 3 * CHUNK_BYTES };

    const int wsel = blockIdx.y;
    const __half* Asrc = g_xh;
    const __half* Wsrc = g_wh + wsel * (EDIM * EDIM);
    __half* Yh = (wsel == 0) ? g_xq : (wsel == 1) ? g_xk : g_xv;

    const int tid  = threadIdx.x;
    const int lane = tid & 31;
    const int w    = tid >> 5;
    const int gid  = lane >> 2;
    const int tig  = lane & 3;
    const int row0 = blockIdx.x * 128;
    const int row_base = (w & 3) << 5;
    const int col_base = (w >> 2) << 6;

#if __CUDA_ARCH__ >= 900
    cudaGridDependencySynchronize();   // wait for k_convert's writes
#endif

    fill_chunk<128, 256>(Ab[0], Asrc, row0, 0, NTOT, tid);
    fill_chunk<128, 256>(Wb[0], Wsrc, 0, 0, 128, tid);
    CP_COMMIT();
    fill_chunk<128, 256>(Ab[1], Asrc, row0, 64, NTOT, tid);
    fill_chunk<128, 256>(Wb[1], Wsrc, 0, 64, 128, tid);
    CP_COMMIT();

    const int l7 = lane & 7;
    const int a_row_sel = ((lane >> 3) & 1) << 3;
    const int a_k_sel   = (lane >> 4) << 3;
    const int b_row_sel = (lane >> 4) << 3;
    const int b_k_sel   = ((lane >> 3) & 1) << 3;
    uint32_t a_off[2], b_off[4];
#pragma unroll
    for (int mt = 0; mt < 2; mt++)
        a_off[mt] = (uint32_t)((row_base + (mt << 4) + a_row_sel + l7) * LDROW + a_k_sel) * 2;
#pragma unroll
    for (int tp = 0; tp < 4; tp++)
        b_off[tp] = (uint32_t)((col_base + (tp << 4) + b_row_sel + l7) * LDROW + b_k_sel) * 2;

    float acc[2][8][4];
#pragma unroll
    for (int mt = 0; mt < 2; mt++)
#pragma unroll
        for (int t = 0; t < 8; t++)
#pragma unroll
            for (int c = 0; c < 4; c++) acc[mt][t][c] = 0.f;

#pragma unroll
    for (int step = 0; step < 2; step++) {
        if (step == 0) { CP_WAIT(1); } else { CP_WAIT(0); }
        __syncthreads();
        const uint32_t Ac = Ab[step], Wc = Wb[step];
#pragma unroll
        for (int ks = 0; ks < 4; ks++) {
            const uint32_t kofs = ks * 32;
            uint32_t a[2][4], b[8][2];
#pragma unroll
            for (int mt = 0; mt < 2; mt++)
                asm volatile(
                    "ldmatrix.sync.aligned.m8n8.x4.shared.b16 {%0,%1,%2,%3}, [%4];"
                    : "=r"(a[mt][0]), "=r"(a[mt][1]), "=r"(a[mt][2]), "=r"(a[mt][3])
                    : "r"(Ac + a_off[mt] + kofs));
#pragma unroll
            for (int tp = 0; tp < 4; tp++)
                asm volatile(
                    "ldmatrix.sync.aligned.m8n8.x4.shared.b16 {%0,%1,%2,%3}, [%4];"
                    : "=r"(b[2 * tp][0]), "=r"(b[2 * tp][1]),
                      "=r"(b[2 * tp + 1][0]), "=r"(b[2 * tp + 1][1])
                    : "r"(Wc + b_off[tp] + kofs));
#pragma unroll
            for (int mt = 0; mt < 2; mt++)
#pragma unroll
                for (int t = 0; t < 8; t++)
                    asm volatile(
                        "mma.sync.aligned.m16n8k16.row.col.f32.f16.f16.f32 "
                        "{%0,%1,%2,%3}, {%4,%5,%6,%7}, {%8,%9}, {%0,%1,%2,%3};"
                        : "+f"(acc[mt][t][0]), "+f"(acc[mt][t][1]),
                          "+f"(acc[mt][t][2]), "+f"(acc[mt][t][3])
                        : "r"(a[mt][0]), "r"(a[mt][1]), "r"(a[mt][2]), "r"(a[mt][3]),
                          "r"(b[t][0]), "r"(b[t][1]));
        }
    }

#pragma unroll
    for (int mt = 0; mt < 2; mt++) {
        int r0g = row0 + row_base + (mt << 4) + gid;
#pragma unroll
        for (int t = 0; t < 8; t++) {
            int col = col_base + (t << 3) + (tig << 1);
            if (r0g < NTOT) {
                __half2 hv = __floats2half2_rn(acc[mt][t][0], acc[mt][t][1]);
                *(uint32_t*)(Yh + (size_t)r0g * EDIM + col) = *(uint32_t*)&hv;
            }
            if (r0g + 8 < NTOT) {
                __half2 hv = __floats2half2_rn(acc[mt][t][2], acc[mt][t][3]);
                *(uint32_t*)(Yh + (size_t)(r0g + 8) * EDIM + col) = *(uint32_t*)&hv;
            }
        }
    }
#if __CUDA_ARCH__ >= 900
    cudaTriggerProgrammaticLaunchCompletion();
#endif
}

// ---------------------------------------------------------------------------
// Attention (round-15 proven version): smem s_g + preloaded V registers +
// quad-shuffle probs. PDL: idx gather pre-sync (input), rest post-sync.
// ---------------------------------------------------------------------------
__global__ __launch_bounds__(128) void k_attn(const int* __restrict__ idx)
{
    const int warp = threadIdx.x >> 5;
    const int lane = threadIdx.x & 31;
    const int p = blockIdx.x * 4 + warp;
    const int b = (p >= NV) ? 1 : 0;

    __shared__ int s_g[4][KNN];

    // Pre-sync: idx is a harness input, independent of k_qkv.
    if (lane < KNN) {
        int n = idx[(size_t)p * KNN + lane];
        n = (n < 0) ? 0 : (n >= NV ? NV - 1 : n);
        s_g[warp][lane] = b * NV + n;
    }

#if __CUDA_ARCH__ >= 900
    cudaGridDependencySynchronize();   // wait for k_qkv's g_xq/g_xk/g_xv
#endif
    __syncwarp();

    const int h = lane >> 2;
    const int j = lane & 3;
    const size_t doff = (size_t)(h << 4) + (j << 2);

    uint2 vraw[KNN];
#pragma unroll
    for (int k = 0; k < KNN; k++) {
        int gk = s_g[warp][k];
        vraw[k] = *(const uint2*)(g_xv + (size_t)gk * EDIM + doff);
    }
    uint2 craw = *(const uint2*)(g_xv + (size_t)p * EDIM + doff);

    float qr[16];
    {
        const uint4* qp = (const uint4*)(g_xq + (size_t)p * EDIM + (h << 4));
        uint4 qu[2] = { qp[0], qp[1] };
        const __half2* qh = (const __half2*)qu;
#pragma unroll
        for (int c = 0; c < 8; c++) {
            float2 f = __half22float2(qh[c]);
            qr[2 * c] = f.x; qr[2 * c + 1] = f.y;
        }
    }

    float sc[4];
#pragma unroll
    for (int i = 0; i < 4; i++) {
        int k = (j << 2) | i;
        int gk = s_g[warp][k];
        const uint4* kp = (const uint4*)(g_xk + (size_t)gk * EDIM + (h << 4));
        uint4 ku[2] = { kp[0], kp[1] };
        const __half2* kh = (const __half2*)ku;
        float d = 0.f;
#pragma unroll
        for (int c = 0; c < 8; c++) {
            float2 f = __half22float2(kh[c]);
            d += qr[2 * c] * f.x + qr[2 * c + 1] * f.y;
        }
        sc[i] = d * 0.25f;  // 1/sqrt(hd=16)
    }

    float m = fmaxf(fmaxf(sc[0], sc[1]), fmaxf(sc[2], sc[3]));
    m = fmaxf(m, __shfl_xor_sync(0xffffffffu, m, 1));
    m = fmaxf(m, __shfl_xor_sync(0xffffffffu, m, 2));
    float s = 0.f;
#pragma unroll
    for (int i = 0; i < 4; i++) { sc[i] = __expf(sc[i] - m); s += sc[i]; }
    s += __shfl_xor_sync(0xffffffffu, s, 1);
    s += __shfl_xor_sync(0xffffffffu, s, 2);
    float rinv = 1.f / s;
#pragma unroll
    for (int i = 0; i < 4; i++) sc[i] *= rinv;   // lane (h,j) holds p[k=4j+i]

    float2 c0 = __half22float2(*(__half2*)&craw.x);
    float2 c1 = __half22float2(*(__half2*)&craw.y);
    float ax = -c0.x, ay = -c0.y, az = -c1.x, aw = -c1.y;
#pragma unroll
    for (int jp = 0; jp < 4; jp++)
#pragma unroll
        for (int i = 0; i < 4; i++) {
            float pk = __shfl_sync(0xffffffffu, sc[i], (h << 2) | jp);
            uint2 raw = vraw[(jp << 2) | i];
            float2 f0 = __half22float2(*(__half2*)&raw.x);
            float2 f1 = __half22float2(*(__half2*)&raw.y);
            ax += pk * f0.x; ay += pk * f0.y; az += pk * f1.x; aw += pk * f1.y;
        }
    __half2 o0 = __floats2half2_rn(ax, ay);
    __half2 o1 = __floats2half2_rn(az, aw);
    *(uint2*)(g_att + (size_t)p * EDIM + doff) =
        make_uint2(*(uint32_t*)&o0, *(uint32_t*)&o1);
#if __CUDA_ARCH__ >= 900
    cudaTriggerProgrammaticLaunchCompletion();
#endif
}

// ---------------------------------------------------------------------------
// Out-proj GEMM. PDL: Wo fill + x prefetch pre-sync, then g_att fills.
// ---------------------------------------------------------------------------
__global__ __launch_bounds__(256) void k_out_f(
    const float* __restrict__ x, float* __restrict__ out)
{
    extern __shared__ __half sm[];
    uint32_t sbase = (uint32_t)__cvta_generic_to_shared(sm);
    uint32_t Ab[2] = { sbase,                 sbase + ACH_BYTES };
    uint32_t Wb[2] = { sbase + 2 * ACH_BYTES, sbase + 2 * ACH_BYTES + CHUNK_BYTES };

    const __half* Wsrc = g_wh + 3 * (EDIM * EDIM);

    const int tid  = threadIdx.x;
    const int lane = tid & 31;
    const int w    = tid >> 5;
    const int gid  = lane >> 2;
    const int tig  = lane & 3;
    const int row0 = blockIdx.x * 64;
    const int row_base = (w & 3) << 4;   // 0,16,32,48
    const int col_base = (w >> 2) << 6;  // 0,64

    // Pre-sync: Wo fill (transitively complete) + residual-x prefetch (input).
    fill_chunk<128, 256>(Wb[0], Wsrc, 0, 0, 128, tid);
    fill_chunk<128, 256>(Wb[1], Wsrc, 0, 64, 128, tid);
    CP_COMMIT();                                       // g0

    const int r0g = row0 + row_base + gid;
    const bool v_lo = (r0g < NTOT);
    const bool v_hi = (r0g + 8 < NTOT);
    float2 xr[2][8];
#pragma unroll
    for (int t = 0; t < 8; t++) {
        int col = col_base + (t << 3) + (tig << 1);
        xr[0][t] = v_lo ? *(const float2*)(x + (size_t)r0g * EDIM + col)
                        : make_float2(0.f, 0.f);
        xr[1][t] = v_hi ? *(const float2*)(x + (size_t)(r0g + 8) * EDIM + col)
                        : make_float2(0.f, 0.f);
    }

#if __CUDA_ARCH__ >= 900
    cudaGridDependencySynchronize();   // wait for k_attn's g_att
#endif

    fill_chunk<64, 256>(Ab[0], g_att, row0, 0, NTOT, tid);
    CP_COMMIT();                                       // g1
    fill_chunk<64, 256>(Ab[1], g_att, row0, 64, NTOT, tid);
    CP_COMMIT();                                       // g2

    const int l7 = lane & 7;
    const int a_row_sel = ((lane >> 3) & 1) << 3;
    const int a_k_sel   = (lane >> 4) << 3;
    const int b_row_sel = (lane >> 4) << 3;
    const int b_k_sel   = ((lane >> 3) & 1) << 3;
    uint32_t a_off  = (uint32_t)((row_base + a_row_sel + l7) * LDROW + a_k_sel) * 2;
    uint32_t b_off[4];
#pragma unroll
    for (int tp = 0; tp < 4; tp++)
        b_off[tp] = (uint32_t)((col_base + (tp << 4) + b_row_sel + l7) * LDROW + b_k_sel) * 2;

    float acc[8][4];
#pragma unroll
    for (int t = 0; t < 8; t++)
#pragma unroll
        for (int c = 0; c < 4; c++) acc[t][c] = 0.f;

#pragma unroll
    for (int step = 0; step < 2; step++) {
        if (step == 0) { CP_WAIT(1); } else { CP_WAIT(0); }
        __syncthreads();
        const uint32_t Ac = Ab[step], Wc = Wb[step];
#pragma unroll
        for (int ks = 0; ks < 4; ks++) {
            const uint32_t kofs = ks * 32;
            uint32_t a[4], b[8][2];
            asm volatile(
                "ldmatrix.sync.aligned.m8n8.x4.shared.b16 {%0,%1,%2,%3}, [%4];"
                : "=r"(a[0]), "=r"(a[1]), "=r"(a[2]), "=r"(a[3])
                : "r"(Ac + a_off + kofs));
#pragma unroll
            for (int tp = 0; tp < 4; tp++)
                asm volatile(
                    "ldmatrix.sync.aligned.m8n8.x4.shared.b16 {%0,%1,%2,%3}, [%4];"
                    : "=r"(b[2 * tp][0]), "=r"(b[2 * tp][1]),
                      "=r"(b[2 * tp + 1][0]), "=r"(b[2 * tp + 1][1])
                    : "r"(Wc + b_off[tp] + kofs));
#pragma unroll
            for (int t = 0; t < 8; t++)
                asm volatile(
                    "mma.sync.aligned.m16n8k16.row.col.f32.f16.f16.f32 "
                    "{%0,%1,%2,%3}, {%4,%5,%6,%7}, {%8,%9}, {%0,%1,%2,%3};"
                    : "+f"(acc[t][0]), "+f"(acc[t][1]), "+f"(acc[t][2]), "+f"(acc[t][3])
                    : "r"(a[0]), "r"(a[1]), "r"(a[2]), "r"(a[3]),
                      "r"(b[t][0]), "r"(b[t][1]));
        }
    }

#pragma unroll
    for (int t = 0; t < 8; t++) {
        int col = col_base + (t << 3) + (tig << 1);
        if (v_lo) {
            size_t off = (size_t)r0g * EDIM + col;
            *(float2*)(out + off) =
                make_float2(acc[t][0] + xr[0][t].x, acc[t][1] + xr[0][t].y);
        }
        if (v_hi) {
            size_t off = (size_t)(r0g + 8) * EDIM + col;
            *(float2*)(out + off) =
                make_float2(acc[t][2] + xr[1][t].x, acc[t][3] + xr[1][t].y);
        }
    }
}

// ---------------------------------------------------------------------------
// Launch with PDL.
// Inputs (metadata order): x[f32], idx[i32], w_q, w_k, w_v, w_o [f32]
// ---------------------------------------------------------------------------
extern "C" void kernel_launch(void* const* d_in, const int* in_sizes, int n_in,
                              void* d_out, int out_size)
{
    const float* x   = (const float*)d_in[0];
    const int*   idx = (const int*)d_in[1];
    const float* wq  = (const float*)d_in[2];
    const float* wk  = (const float*)d_in[3];
    const float* wv  = (const float*)d_in[4];
    const float* wo  = (const float*)d_in[5];
    float*       out = (float*)d_out;

    cudaFuncSetAttribute(k_qkv_f, cudaFuncAttributeMaxDynamicSharedMemorySize, SMEM_QKV);
    cudaFuncSetAttribute(k_out_f, cudaFuncAttributeMaxDynamicSharedMemorySize, SMEM_OUT);

    cudaLaunchAttribute pdl[1];
    pdl[0].id = cudaLaunchAttributeProgrammaticStreamSerialization;
    pdl[0].val.programmaticStreamSerializationAllowed = 1;

    k_convert<<<1616, 256>>>(x, wq, wk, wv, wo);

    {
        cudaLaunchConfig_t cfg = {};
        cfg.gridDim = dim3((NTOT + 127) / 128, 3);
        cfg.blockDim = dim3(256);
        cfg.dynamicSmemBytes = SMEM_QKV;
        cfg.stream = 0;
        cfg.attrs = pdl;
        cfg.numAttrs = 1;
        cudaLaunchKernelEx(&cfg, k_qkv_f);
    }
    {
        cudaLaunchConfig_t cfg = {};
        cfg.gridDim = dim3(NTOT / 4);
        cfg.blockDim = dim3(128);
        cfg.dynamicSmemBytes = 0;
        cfg.stream = 0;
        cfg.attrs = pdl;
        cfg.numAttrs = 1;
        cudaLaunchKernelEx(&cfg, k_attn, idx);
    }
    {
        cudaLaunchConfig_t cfg = {};
        cfg.gridDim = dim3((NTOT + 63) / 64);
        cfg.blockDim = dim3(256);
        cfg.dynamicSmemBytes = SMEM_OUT;
        cfg.stream = 0;
        cfg.attrs = pdl;
        cfg.numAttrs = 1;
        cudaLaunchKernelEx(&cfg, k_out_f, x, out);
    }
}